// round 16
// baseline (speedup 1.0000x reference)
#include <cuda_runtime.h>
#include <cuda_bf16.h>
#include <cstdint>

#define NN 4096
#define FDIM 256
#define ALPHA_LR 0.01f
#define NEG_INF_V -9.0e15f
#define ROWS 64
#define JSPLIT 4

// Scratch (allocation-free rule: __device__ globals)
__device__ __align__(16) float g_Wh[NN * FDIM];
__device__ float g_f1[NN];
__device__ float g_f2[NN];
__device__ float g_m[NN];
__device__ __align__(16) uint32_t g_mask[NN * NN / 32];   // 2MB bitmask
__device__ __align__(16) uint32_t g_whh[FDIM * NN / 2];   // WhT hi [f][j/2]
__device__ __align__(16) uint32_t g_whl[FDIM * NN / 2];   // WhT lo [f][j/2]
__device__ __align__(16) float g_pacc[JSPLIT * NN * FDIM]; // partial numerators
__device__ float g_lpart[JSPLIT * NN];                     // partial l sums
// packed h buffers (ping/pong): [m][k/2] bf16x2 hi/lo
__device__ __align__(16) uint32_t g_xh[NN * FDIM / 2];
__device__ __align__(16) uint32_t g_xl[NN * FDIM / 2];
__device__ __align__(16) uint32_t g_yh[NN * FDIM / 2];
__device__ __align__(16) uint32_t g_yl[NN * FDIM / 2];
// transposed weights: [4][n][k/2] bf16x2 hi/lo
__device__ __align__(16) uint32_t g_wth[4 * FDIM * FDIM / 2];
__device__ __align__(16) uint32_t g_wtl[4 * FDIM * FDIM / 2];

__device__ __forceinline__ uint32_t smem_u32(const void* p) {
    uint32_t a;
    asm("{ .reg .u64 t; cvta.to.shared.u64 t, %1; cvt.u32.u64 %0, t; }"
        : "=r"(a) : "l"(p));
    return a;
}

__device__ __forceinline__ void cp_async16(uint32_t s, const void* g) {
    asm volatile("cp.async.cg.shared.global [%0], [%1], 16;" :: "r"(s), "l"(g));
}
#define CP_COMMIT() asm volatile("cp.async.commit_group;" ::: "memory")
#define CP_WAIT0()  asm volatile("cp.async.wait_group 0;" ::: "memory")

__device__ __forceinline__ void split2(float pe, float po,
                                       uint32_t& hw, uint32_t& lw) {
    __nv_bfloat16 he = __float2bfloat16(pe);
    __nv_bfloat16 ho = __float2bfloat16(po);
    float re = pe - __bfloat162float(he);
    float ro = po - __bfloat162float(ho);
    __nv_bfloat162 h2 = __halves2bfloat162(he, ho);
    __nv_bfloat162 l2 = __floats2bfloat162_rn(re, ro);
    hw = *reinterpret_cast<uint32_t*>(&h2);
    lw = *reinterpret_cast<uint32_t*>(&l2);
}

__device__ __forceinline__ void mma_bf16(float& d0, float& d1, float& d2, float& d3,
                                         uint32_t a0, uint32_t a1,
                                         uint32_t a2, uint32_t a3,
                                         uint32_t b0, uint32_t b1) {
    asm volatile(
        "mma.sync.aligned.m16n8k16.row.col.f32.bf16.bf16.f32 "
        "{%0,%1,%2,%3}, {%4,%5,%6,%7}, {%8,%9}, {%0,%1,%2,%3};"
        : "+f"(d0), "+f"(d1), "+f"(d2), "+f"(d3)
        : "r"(a0), "r"(a1), "r"(a2), "r"(a3), "r"(b0), "r"(b1));
}

__device__ __forceinline__ void ldsm_x4(uint32_t& r0, uint32_t& r1,
                                        uint32_t& r2, uint32_t& r3,
                                        uint32_t addr) {
    asm volatile("ldmatrix.sync.aligned.m8n8.x4.shared.b16 {%0,%1,%2,%3}, [%4];"
                 : "=r"(r0), "=r"(r1), "=r"(r2), "=r"(r3) : "r"(addr));
}

// ---------------------------------------------------------------------------
// Pack adj into bitmask
// ---------------------------------------------------------------------------
__global__ void pack_kernel(const int* __restrict__ adj,
                            uint32_t* __restrict__ mask) {
    const int lane = threadIdx.x & 31;
    const int gw = (blockIdx.x * 256 + threadIdx.x) >> 5;
    #pragma unroll 4
    for (int k = 0; k < 64; k++) {
        size_t word = (size_t)gw * 64 + k;
        int v = adj[word * 32 + lane];
        uint32_t b = __ballot_sync(0xffffffffu, v > 0);
        if (lane == 0) mask[word] = b;
    }
}

// ---------------------------------------------------------------------------
// hconv: X fp32 [4096][256] -> packed bf16x2 hi/lo [m][k/2]
// ---------------------------------------------------------------------------
__global__ __launch_bounds__(256)
void hconv_kernel(const float* __restrict__ X,
                  uint32_t* __restrict__ xh,
                  uint32_t* __restrict__ xl) {
    int v = blockIdx.x * 256 + threadIdx.x;
    int row = v >> 5;
    int c = v & 31;
    const float* src = &X[(size_t)row * FDIM + c * 8];
    float4 a = *reinterpret_cast<const float4*>(src);
    float4 b = *reinterpret_cast<const float4*>(src + 4);
    uint32_t hw[4], lw[4];
    split2(a.x, a.y, hw[0], lw[0]);
    split2(a.z, a.w, hw[1], lw[1]);
    split2(b.x, b.y, hw[2], lw[2]);
    split2(b.z, b.w, hw[3], lw[3]);
    size_t off = (size_t)row * 128 + c * 4;
    *reinterpret_cast<uint4*>(&xh[off]) = make_uint4(hw[0], hw[1], hw[2], hw[3]);
    *reinterpret_cast<uint4*>(&xl[off]) = make_uint4(lw[0], lw[1], lw[2], lw[3]);
}

// ---------------------------------------------------------------------------
// wtconv: W fp32 [k][n] -> WT packed [n][k/2] hi/lo. blockIdx.z picks matrix.
// ---------------------------------------------------------------------------
__global__ __launch_bounds__(256)
void wtconv_kernel(const float* __restrict__ W0, const float* __restrict__ W1,
                   const float* __restrict__ W2, const float* __restrict__ W3,
                   uint32_t* __restrict__ wth, uint32_t* __restrict__ wtl) {
    __shared__ float tile[64][33];
    const float* Ws[4] = {W0, W1, W2, W3};
    const float* W = Ws[blockIdx.z];
    uint32_t* oth = wth + (size_t)blockIdx.z * (FDIM * FDIM / 2);
    uint32_t* otl = wtl + (size_t)blockIdx.z * (FDIM * FDIM / 2);
    const int tid = threadIdx.x;
    const int kt = blockIdx.x * 64;
    const int nt = blockIdx.y * 32;
    {
        int r = tid >> 2;
        int c8 = (tid & 3) * 8;
        float4 v0 = *reinterpret_cast<const float4*>(&W[(size_t)(kt + r) * FDIM + nt + c8]);
        float4 v1 = *reinterpret_cast<const float4*>(&W[(size_t)(kt + r) * FDIM + nt + c8 + 4]);
        tile[r][c8 + 0] = v0.x; tile[r][c8 + 1] = v0.y;
        tile[r][c8 + 2] = v0.z; tile[r][c8 + 3] = v0.w;
        tile[r][c8 + 4] = v1.x; tile[r][c8 + 5] = v1.y;
        tile[r][c8 + 6] = v1.z; tile[r][c8 + 7] = v1.w;
    }
    __syncthreads();
    {
        int n = tid >> 3;
        int kp = (tid & 7) * 4;
        uint32_t hw[4], lw[4];
        #pragma unroll
        for (int q = 0; q < 4; q++) {
            int k = 2 * (kp + q);
            split2(tile[k][n], tile[k + 1][n], hw[q], lw[q]);
        }
        size_t off = (size_t)(nt + n) * (FDIM / 2) + (kt >> 1) + kp;
        *reinterpret_cast<uint4*>(&oth[off]) = make_uint4(hw[0], hw[1], hw[2], hw[3]);
        *reinterpret_cast<uint4*>(&otl[off]) = make_uint4(lw[0], lw[1], lw[2], lw[3]);
    }
}

// ---------------------------------------------------------------------------
// HMMA GEMM: C = A @ W. 64x64 tiles (32 KB/buf, 64 KB -> 2 CTAs/SM),
// grid (4, 64) = 256 CTAs. Warp (mq = w&1, nq = w>>1): 32m x 16n.
// ---------------------------------------------------------------------------
__global__ __launch_bounds__(256, 2)
void gemm_hmma_kernel(const uint32_t* __restrict__ ah,
                      const uint32_t* __restrict__ al,
                      const uint32_t* __restrict__ wth,
                      const uint32_t* __restrict__ wtl,
                      float* __restrict__ Cf,
                      uint32_t* __restrict__ oh,
                      uint32_t* __restrict__ ol,
                      int mode) {
    extern __shared__ __align__(16) uint32_t ws[];
    const int tid  = threadIdx.x;
    const int lane = tid & 31;
    const int warp = tid >> 5;
    const int mq = warp & 1;
    const int nq = warp >> 1;
    const int m0 = blockIdx.y * 64;
    const int n0 = blockIdx.x * 64;
    const uint32_t sbase = smem_u32(ws);

    const int rowA  = lane & 15;
    const int koA   = lane >> 4;
    const int mlocB = lane >> 3;
    const int ntlB  = mlocB >> 1;
    const int koB   = mlocB & 1;
    const int rowBl = lane & 7;
    const int g    = lane >> 2;
    const int tig  = lane & 3;

    float acc[2][2][4] = {};                       // [mt][nt][reg]

    // smem words/buffer: AH 0..2047, AL 2048.., BH 4096.., BL 6144.. (8192)
    auto stage = [&](int kc, int b) {
        uint32_t base = b * 8192u;
        #pragma unroll
        for (int k = 0; k < 4; k++) {              // A: 1024 uint4
            int idx = k * 256 + tid;
            int half = idx >> 9;
            int rem  = idx & 511;
            int r = rem >> 3, c = rem & 7;
            const uint32_t* src = (half ? al : ah) +
                (size_t)(m0 + r) * 128 + kc * 32 + c * 4;
            cp_async16(sbase + (base + half * 2048u + r * 32 + ((c ^ (r & 7)) * 4)) * 4,
                       src);
        }
        #pragma unroll
        for (int k = 0; k < 4; k++) {              // B: 1024 uint4
            int idx = k * 256 + tid;
            int half = idx >> 9;
            int rem  = idx & 511;
            int r = rem >> 3, c = rem & 7;
            const uint32_t* src = (half ? wtl : wth) +
                (size_t)(n0 + r) * 128 + kc * 32 + c * 4;
            cp_async16(sbase + (base + 4096u + half * 2048u + r * 32 +
                                ((c ^ (r & 7)) * 4)) * 4,
                       src);
        }
        CP_COMMIT();
    };

    stage(0, 0);
    CP_WAIT0();
    __syncthreads();

    for (int kc = 0; kc < 4; kc++) {
        if (kc < 3) stage(kc + 1, (kc + 1) & 1);
        const int b = kc & 1;
        const uint32_t AH = sbase + (b * 8192u) * 4;
        const uint32_t AL = AH + 2048u * 4;
        const uint32_t BH = sbase + (b * 8192u + 4096u) * 4;
        const uint32_t BL = BH + 2048u * 4;
        #pragma unroll
        for (int ksl = 0; ksl < 4; ksl++) {
            uint32_t ahf[2][4], alf[2][4];
            #pragma unroll
            for (int mt = 0; mt < 2; mt++) {
                int rin = mq * 32 + mt * 16 + rowA;
                uint32_t off = rin * 128 + (((2 * ksl + koA) ^ (rin & 7)) << 4);
                ldsm_x4(ahf[mt][0], ahf[mt][1], ahf[mt][2], ahf[mt][3], AH + off);
                ldsm_x4(alf[mt][0], alf[mt][1], alf[mt][2], alf[mt][3], AL + off);
            }
            int fin = nq * 16 + ntlB * 8 + rowBl;
            uint32_t boff = fin * 128 + (((2 * ksl + koB) ^ (fin & 7)) << 4);
            uint32_t bh0, bh1, bh2, bh3, bl0, bl1, bl2, bl3;
            ldsm_x4(bh0, bh1, bh2, bh3, BH + boff);
            ldsm_x4(bl0, bl1, bl2, bl3, BL + boff);
            #pragma unroll
            for (int mt = 0; mt < 2; mt++) {
                mma_bf16(acc[mt][0][0], acc[mt][0][1], acc[mt][0][2], acc[mt][0][3],
                         ahf[mt][0], ahf[mt][1], ahf[mt][2], ahf[mt][3], bh0, bh1);
                mma_bf16(acc[mt][0][0], acc[mt][0][1], acc[mt][0][2], acc[mt][0][3],
                         ahf[mt][0], ahf[mt][1], ahf[mt][2], ahf[mt][3], bl0, bl1);
                mma_bf16(acc[mt][0][0], acc[mt][0][1], acc[mt][0][2], acc[mt][0][3],
                         alf[mt][0], alf[mt][1], alf[mt][2], alf[mt][3], bh0, bh1);
                mma_bf16(acc[mt][1][0], acc[mt][1][1], acc[mt][1][2], acc[mt][1][3],
                         ahf[mt][0], ahf[mt][1], ahf[mt][2], ahf[mt][3], bh2, bh3);
                mma_bf16(acc[mt][1][0], acc[mt][1][1], acc[mt][1][2], acc[mt][1][3],
                         ahf[mt][0], ahf[mt][1], ahf[mt][2], ahf[mt][3], bl2, bl3);
                mma_bf16(acc[mt][1][0], acc[mt][1][1], acc[mt][1][2], acc[mt][1][3],
                         alf[mt][0], alf[mt][1], alf[mt][2], alf[mt][3], bh2, bh3);
            }
        }
        if (kc < 3) CP_WAIT0();
        __syncthreads();
    }

    #pragma unroll
    for (int mt = 0; mt < 2; mt++) {
        int r0 = m0 + mq * 32 + mt * 16 + g;
        int r1 = r0 + 8;
        #pragma unroll
        for (int nt = 0; nt < 2; nt++) {
            int f = n0 + nq * 16 + nt * 8 + 2 * tig;
            if (mode == 1) {
                *reinterpret_cast<float2*>(&Cf[(size_t)r0 * FDIM + f]) =
                    make_float2(acc[mt][nt][0], acc[mt][nt][1]);
                *reinterpret_cast<float2*>(&Cf[(size_t)r1 * FDIM + f]) =
                    make_float2(acc[mt][nt][2], acc[mt][nt][3]);
            } else {
                uint32_t hw, lw;
                split2(acc[mt][nt][0], acc[mt][nt][1], hw, lw);
                oh[(size_t)r0 * 128 + (f >> 1)] = hw;
                ol[(size_t)r0 * 128 + (f >> 1)] = lw;
                split2(acc[mt][nt][2], acc[mt][nt][3], hw, lw);
                oh[(size_t)r1 * 128 + (f >> 1)] = hw;
                ol[(size_t)r1 * 128 + (f >> 1)] = lw;
            }
        }
    }
}

// ---------------------------------------------------------------------------
// wfuse: per 64-row slab of Wh -> (a) f1/f2 dot products, (b) transposed
// packed bf16x2 hi/lo [f][j/2]. One Wh read instead of two. Deterministic.
// ---------------------------------------------------------------------------
__global__ __launch_bounds__(256)
void wfuse_kernel(const float* __restrict__ Wh,
                  const float* __restrict__ a,
                  uint32_t* __restrict__ whh,
                  uint32_t* __restrict__ whl,
                  float* __restrict__ f1,
                  float* __restrict__ f2) {
    extern __shared__ float tile[];                // [64][260]
    const int tid = threadIdx.x;
    const int jt = blockIdx.x * 64;

    // load 64 rows x 256 f (4 threads/row, 64 floats each, coalesced)
    {
        int r = tid >> 2;
        int c0 = (tid & 3) * 64;
        const float* src = &Wh[(size_t)(jt + r) * FDIM + c0];
        float* drow = &tile[r * 260 + c0];
        #pragma unroll
        for (int q = 0; q < 16; q++) {
            float4 v = *reinterpret_cast<const float4*>(src + q * 4);
            drow[q * 4 + 0] = v.x; drow[q * 4 + 1] = v.y;
            drow[q * 4 + 2] = v.z; drow[q * 4 + 3] = v.w;
        }
    }
    __syncthreads();

    // f1/f2: quad per row; stride-4 column interleave (conflict-free)
    {
        int r = tid >> 2;
        int cq = tid & 3;
        float s1 = 0.f, s2 = 0.f;
        const float* trow = &tile[r * 260];
        #pragma unroll
        for (int q = 0; q < 64; q++) {
            int c = cq + 4 * q;
            float w = trow[c];
            s1 += w * a[c];
            s2 += w * a[FDIM + c];
        }
        s1 += __shfl_xor_sync(0xffffffffu, s1, 1);
        s1 += __shfl_xor_sync(0xffffffffu, s1, 2);
        s2 += __shfl_xor_sync(0xffffffffu, s2, 1);
        s2 += __shfl_xor_sync(0xffffffffu, s2, 2);
        if (cq == 0) { f1[jt + r] = s1; f2[jt + r] = s2; }
    }

    // transpose + split: thread = feature f, 32 j-pair words
    {
        int f = tid;
        size_t base = (size_t)f * (NN / 2) + (jt >> 1);
        #pragma unroll
        for (int q = 0; q < 32; q++) {
            uint32_t hw, lw;
            split2(tile[(2 * q) * 260 + f], tile[(2 * q + 1) * 260 + f], hw, lw);
            whh[base + q] = hw;
            whl[base + q] = lw;
        }
    }
}

// ---------------------------------------------------------------------------
// Row max via monotonicity
// ---------------------------------------------------------------------------
__global__ __launch_bounds__(256)
void rowmax_kernel(const uint32_t* __restrict__ mask,
                   const float* __restrict__ f1,
                   const float* __restrict__ f2,
                   float* __restrict__ m) {
    __shared__ __align__(16) float f2s[NN];
    __shared__ uint32_t ms[8][128];
    const int tid  = threadIdx.x;
    const int lane = tid & 31;
    const int warp = tid >> 5;
    const int row0 = blockIdx.x * 8;

    #pragma unroll
    for (int k = 0; k < 4; k++) {
        int c = k * 256 + tid;
        reinterpret_cast<float4*>(f2s)[c] =
            reinterpret_cast<const float4*>(f2)[c];
    }
    #pragma unroll
    for (int k = 0; k < 4; k++) {
        int i = k * 256 + tid;
        ms[i >> 7][i & 127] = mask[(size_t)(row0 + (i >> 7)) * 128 + (i & 127)];
    }
    __syncthreads();

    float mx = -1.0e30f;
    #pragma unroll 8
    for (int k = 0; k < 128; k++) {
        uint32_t w = ms[warp][k];
        float v = f2s[k * 32 + lane];
        if ((w >> lane) & 1u) mx = fmaxf(mx, v);
    }
    #pragma unroll
    for (int off = 16; off; off >>= 1)
        mx = fmaxf(mx, __shfl_xor_sync(0xffffffffu, mx, off));
    if (lane == 0) {
        int row = row0 + warp;
        if (mx < -1.0e29f) {
            m[row] = NEG_INF_V;
        } else {
            float s = f1[row] + mx;
            m[row] = s > 0.f ? s : ALPHA_LR * s;
        }
    }
}

// ---------------------------------------------------------------------------
// Fused attention on HMMA (unchanged from R15): 64 rows x 256 f x j-quarter.
// ---------------------------------------------------------------------------
__global__ __launch_bounds__(256, 2)
void attn_kernel(const uint32_t* __restrict__ whh,
                 const uint32_t* __restrict__ whl,
                 const uint32_t* __restrict__ mask,
                 const float* __restrict__ f1,
                 const float* __restrict__ f2,
                 const float* __restrict__ m,
                 float* __restrict__ pacc,
                 float* __restrict__ lpart) {
    extern __shared__ __align__(16) uint32_t ws[];

    const int tid  = threadIdx.x;
    const int lane = tid & 31;
    const int warp = tid >> 5;
    const int g    = lane >> 2;
    const int tig  = lane & 3;
    const int row0 = blockIdx.x * ROWS;
    const int jq   = blockIdx.y;
    const uint32_t sbase = smem_u32(ws);

    const int prow = tid >> 2;
    const int jb8  = (tid & 3) * 8;
    const int grow = row0 + prow;
    const float f1r = f1[grow];
    const float mr  = m[grow];
    const uint32_t* mrow = mask + (size_t)grow * 128 + jq * 32;
    float ls = 0.f;

    float acc[4][4][4] = {};

    const int rowA  = lane & 15;
    const int koA   = lane >> 4;
    const int mlocB = lane >> 3;
    const int ntlB  = mlocB >> 1;
    const int koB   = mlocB & 1;
    const int rowBl = lane & 7;

    float4 fv0, fv1;
    uint32_t mw;

    fv0 = *reinterpret_cast<const float4*>(&f2[jq * 1024 + jb8]);
    fv1 = *reinterpret_cast<const float4*>(&f2[jq * 1024 + jb8 + 4]);
    mw  = mrow[0];
    #pragma unroll
    for (int k = 0; k < 8; k++) {
        int idx = k * 256 + tid;
        int half = idx >> 10;
        int rem  = idx & 1023;
        int f = rem >> 2, c = rem & 3;
        const uint32_t* src = (half ? whl : whh) +
            (size_t)f * (NN / 2) + jq * 512 + c * 4;
        cp_async16(sbase + (half * 4096 + f * 16 + ((c ^ ((f >> 1) & 3)) * 4)) * 4,
                   src);
    }
    CP_COMMIT();
    {
        uint32_t bits = (mw >> jb8) & 0xffu;
        const float fvr[8] = {fv0.x, fv0.y, fv0.z, fv0.w,
                              fv1.x, fv1.y, fv1.z, fv1.w};
        float pv[8];
        #pragma unroll
        for (int q = 0; q < 8; q++) {
            float s = f1r + fvr[q];
            float e = s > 0.f ? s : ALPHA_LR * s;
            float sc = ((bits >> q) & 1u) ? e : NEG_INF_V;
            pv[q] = __expf(sc - mr);
            ls += pv[q];
        }
        uint32_t hw[4], lw[4];
        #pragma unroll
        for (int u = 0; u < 4; u++) split2(pv[2 * u], pv[2 * u + 1], hw[u], lw[u]);
        int cb = tid & 3;
        uint32_t* ph = ws + 16384 + prow * 16;
        uint32_t* pl = ph + 1024;
        uint32_t so = (cb ^ ((prow >> 1) & 3)) * 4;
        *reinterpret_cast<uint4*>(ph + so) = make_uint4(hw[0], hw[1], hw[2], hw[3]);
        *reinterpret_cast<uint4*>(pl + so) = make_uint4(lw[0], lw[1], lw[2], lw[3]);
    }
    fv0 = *reinterpret_cast<const float4*>(&f2[jq * 1024 + 32 + jb8]);
    fv1 = *reinterpret_cast<const float4*>(&f2[jq * 1024 + 32 + jb8 + 4]);
    mw  = mrow[1];
    CP_WAIT0();
    __syncthreads();

    for (int t = 0; t < 32; t++) {
        if (t < 31) {
            const int b = (t + 1) & 1;
            #pragma unroll
            for (int k = 0; k < 8; k++) {
                int idx = k * 256 + tid;
                int half = idx >> 10;
                int rem  = idx & 1023;
                int f = rem >> 2, c = rem & 3;
                const uint32_t* src = (half ? whl : whh) +
                    (size_t)f * (NN / 2) + jq * 512 + (t + 1) * 16 + c * 4;
                cp_async16(sbase + (b * 8192 + half * 4096 + f * 16 +
                                    ((c ^ ((f >> 1) & 3)) * 4)) * 4,
                           src);
            }
            CP_COMMIT();
            uint32_t bits = (mw >> jb8) & 0xffu;
            const float fvr[8] = {fv0.x, fv0.y, fv0.z, fv0.w,
                                  fv1.x, fv1.y, fv1.z, fv1.w};
            float pv[8];
            #pragma unroll
            for (int q = 0; q < 8; q++) {
                float s = f1r + fvr[q];
                float e = s > 0.f ? s : ALPHA_LR * s;
                float sc = ((bits >> q) & 1u) ? e : NEG_INF_V;
                pv[q] = __expf(sc - mr);
                ls += pv[q];
            }
            uint32_t hw[4], lw[4];
            #pragma unroll
            for (int u = 0; u < 4; u++)
                split2(pv[2 * u], pv[2 * u + 1], hw[u], lw[u]);
            int cb = tid & 3;
            uint32_t* ph = ws + 16384 + b * 2048 + prow * 16;
            uint32_t* pl = ph + 1024;
            uint32_t so = (cb ^ ((prow >> 1) & 3)) * 4;
            *reinterpret_cast<uint4*>(ph + so) =
                make_uint4(hw[0], hw[1], hw[2], hw[3]);
            *reinterpret_cast<uint4*>(pl + so) =
                make_uint4(lw[0], lw[1], lw[2], lw[3]);
            int tn = (t + 2) & 31;
            fv0 = *reinterpret_cast<const float4*>(&f2[jq * 1024 + tn * 32 + jb8]);
            fv1 = *reinterpret_cast<const float4*>(&f2[jq * 1024 + tn * 32 + jb8 + 4]);
            mw  = mrow[tn];
        }

        {
            const int b = t & 1;
            const uint32_t BH = sbase + (b * 8192) * 4;
            const uint32_t BL = BH + 4096 * 4;
            const uint32_t PH = sbase + (16384 + b * 2048) * 4;
            const uint32_t PL = PH + 1024 * 4;
            #pragma unroll
            for (int ks = 0; ks < 2; ks++) {
                uint32_t ah[4][4], al[4][4];
                #pragma unroll
                for (int mt = 0; mt < 4; mt++) {
                    int rin = mt * 16 + rowA;
                    uint32_t off = rin * 64 +
                        (((2 * ks + koA) ^ ((rin >> 1) & 3)) << 4);
                    ldsm_x4(ah[mt][0], ah[mt][1], ah[mt][2], ah[mt][3], PH + off);
                    ldsm_x4(al[mt][0], al[mt][1], al[mt][2], al[mt][3], PL + off);
                }
                #pragma unroll
                for (int ntp = 0; ntp < 2; ntp++) {
                    int fin = warp * 32 + ntp * 16 + ntlB * 8 + rowBl;
                    uint32_t off = fin * 64 +
                        (((2 * ks + koB) ^ ((fin >> 1) & 3)) << 4);
                    uint32_t bh0, bh1, bh2, bh3, bl0, bl1, bl2, bl3;
                    ldsm_x4(bh0, bh1, bh2, bh3, BH + off);
                    ldsm_x4(bl0, bl1, bl2, bl3, BL + off);
                    #pragma unroll
                    for (int mt = 0; mt < 4; mt++) {
                        int n0 = ntp * 2;
                        mma_bf16(acc[mt][n0][0], acc[mt][n0][1],
                                 acc[mt][n0][2], acc[mt][n0][3],
                                 ah[mt][0], ah[mt][1], ah[mt][2], ah[mt][3],
                                 bh0, bh1);
                        mma_bf16(acc[mt][n0][0], acc[mt][n0][1],
                                 acc[mt][n0][2], acc[mt][n0][3],
                                 ah[mt][0], ah[mt][1], ah[mt][2], ah[mt][3],
                                 bl0, bl1);
                        mma_bf16(acc[mt][n0][0], acc[mt][n0][1],
                                 acc[mt][n0][2], acc[mt][n0][3],
                                 al[mt][0], al[mt][1], al[mt][2], al[mt][3],
                                 bh0, bh1);
                        mma_bf16(acc[mt][n0 + 1][0], acc[mt][n0 + 1][1],
                                 acc[mt][n0 + 1][2], acc[mt][n0 + 1][3],
                                 ah[mt][0], ah[mt][1], ah[mt][2], ah[mt][3],
                                 bh2, bh3);
                        mma_bf16(acc[mt][n0 + 1][0], acc[mt][n0 + 1][1],
                                 acc[mt][n0 + 1][2], acc[mt][n0 + 1][3],
                                 ah[mt][0], ah[mt][1], ah[mt][2], ah[mt][3],
                                 bl2, bl3);
                        mma_bf16(acc[mt][n0 + 1][0], acc[mt][n0 + 1][1],
                                 acc[mt][n0 + 1][2], acc[mt][n0 + 1][3],
                                 al[mt][0], al[mt][1], al[mt][2], al[mt][3],
                                 bh2, bh3);
                    }
                }
            }
        }
        if (t < 31) CP_WAIT0();
        __syncthreads();
    }

    ls += __shfl_xor_sync(0xffffffffu, ls, 1);
    ls += __shfl_xor_sync(0xffffffffu, ls, 2);
    if ((tid & 3) == 0) lpart[(size_t)jq * NN + grow] = ls;

    #pragma unroll
    for (int mt = 0; mt < 4; mt++) {
        int r0 = row0 + mt * 16 + g;
        int r1 = r0 + 8;
        #pragma unroll
        for (int nt = 0; nt < 4; nt++) {
            int f = warp * 32 + nt * 8 + 2 * tig;
            *reinterpret_cast<float2*>(
                &pacc[((size_t)jq * NN + r0) * FDIM + f]) =
                make_float2(acc[mt][nt][0], acc[mt][nt][1]);
            *reinterpret_cast<float2*>(
                &pacc[((size_t)jq * NN + r1) * FDIM + f]) =
                make_float2(acc[mt][nt][2], acc[mt][nt][3]);
        }
    }
}

// ---------------------------------------------------------------------------
// Combine 4 partials: v = ELU(Σnum/Σl); fp32 out (mode 1) or packed h (mode 0)
// ---------------------------------------------------------------------------
__global__ void combine_kernel(const float* __restrict__ pacc,
                               const float* __restrict__ lpart,
                               float* __restrict__ outf,
                               uint32_t* __restrict__ oh,
                               uint32_t* __restrict__ ol,
                               int mode) {
    int v = blockIdx.x * 256 + threadIdx.x;
    int row = v >> 6;
    int c = (v & 63) * 4;
    float4 o = make_float4(0.f, 0.f, 0.f, 0.f);
    float lsum = 0.f;
    #pragma unroll
    for (int q = 0; q < JSPLIT; q++) {
        float4 a = *reinterpret_cast<const float4*>(
            &pacc[((size_t)q * NN + row) * FDIM + c]);
        o.x += a.x; o.y += a.y; o.z += a.z; o.w += a.w;
        lsum += lpart[(size_t)q * NN + row];
    }
    float inv = 1.f / lsum;
    o.x *= inv; o.y *= inv; o.z *= inv; o.w *= inv;
    o.x = o.x > 0.f ? o.x : (__expf(o.x) - 1.f);
    o.y = o.y > 0.f ? o.y : (__expf(o.y) - 1.f);
    o.z = o.z > 0.f ? o.z : (__expf(o.z) - 1.f);
    o.w = o.w > 0.f ? o.w : (__expf(o.w) - 1.f);
    if (mode == 1) {
        *reinterpret_cast<float4*>(&outf[(size_t)row * FDIM + c]) = o;
    } else {
        uint32_t h0, l0, h1, l1;
        split2(o.x, o.y, h0, l0);
        split2(o.z, o.w, h1, l1);
        size_t off = (size_t)row * 128 + (c >> 1);
        *reinterpret_cast<uint2*>(&oh[off]) = make_uint2(h0, h1);
        *reinterpret_cast<uint2*>(&ol[off]) = make_uint2(l0, l1);
    }
}

// ---------------------------------------------------------------------------
extern "C" void kernel_launch(void* const* d_in, const int* in_sizes, int n_in,
                              void* d_out, int out_size) {
    const float* input = (const float*)d_in[0];
    const int*   adj   = (const int*)  d_in[1];
    const float* W0    = (const float*)d_in[2];
    const float* Wl[3] = {(const float*)d_in[3], (const float*)d_in[5],
                          (const float*)d_in[7]};
    const float* al[3] = {(const float*)d_in[4], (const float*)d_in[6],
                          (const float*)d_in[8]};
    float* out = (float*)d_out;

    float *Wh, *f1, *f2, *m, *pacc, *lpart;
    uint32_t *mask, *whh, *whl, *xh, *xl, *yh, *yl, *wth, *wtl;
    cudaGetSymbolAddress((void**)&Wh,    g_Wh);
    cudaGetSymbolAddress((void**)&f1,    g_f1);
    cudaGetSymbolAddress((void**)&f2,    g_f2);
    cudaGetSymbolAddress((void**)&m,     g_m);
    cudaGetSymbolAddress((void**)&mask,  g_mask);
    cudaGetSymbolAddress((void**)&whh,   g_whh);
    cudaGetSymbolAddress((void**)&whl,   g_whl);
    cudaGetSymbolAddress((void**)&pacc,  g_pacc);
    cudaGetSymbolAddress((void**)&lpart, g_lpart);
    cudaGetSymbolAddress((void**)&xh,    g_xh);
    cudaGetSymbolAddress((void**)&xl,    g_xl);
    cudaGetSymbolAddress((void**)&yh,    g_yh);
    cudaGetSymbolAddress((void**)&yl,    g_yl);
    cudaGetSymbolAddress((void**)&wth,   g_wth);
    cudaGetSymbolAddress((void**)&wtl,   g_wtl);

    const int ATTN_SMEM  = 20480 * 4;              // 80 KB -> 2 CTAs/SM
    const int GEMM_SMEM  = 16384 * 4;              // 64 KB -> 2 CTAs/SM
    const int WFUSE_SMEM = 64 * 260 * 4;           // 66.6 KB
    static bool attr_set = false;
    if (!attr_set) {
        cudaFuncSetAttribute(attn_kernel,
                             cudaFuncAttributeMaxDynamicSharedMemorySize,
                             ATTN_SMEM);
        cudaFuncSetAttribute(gemm_hmma_kernel,
                             cudaFuncAttributeMaxDynamicSharedMemorySize,
                             GEMM_SMEM);
        cudaFuncSetAttribute(wfuse_kernel,
                             cudaFuncAttributeMaxDynamicSharedMemorySize,
                             WFUSE_SMEM);
        attr_set = true;
    }

    dim3 gemmGrid(FDIM / 64, NN / 64);             // (4, 64) = 256 CTAs
    dim3 wtGrid(FDIM / 64, FDIM / 32, 4);          // (4, 8, 4)
    dim3 attnGrid(NN / ROWS, JSPLIT);              // (64, 4) = 256 CTAs

    pack_kernel<<<1024, 256>>>(adj, mask);
    wtconv_kernel<<<wtGrid, 256>>>(W0, Wl[0], Wl[1], Wl[2], wth, wtl);
    hconv_kernel<<<512, 256>>>(input, xh, xl);
    gemm_hmma_kernel<<<gemmGrid, 256, GEMM_SMEM>>>(
        xh, xl, wth, wtl, nullptr, yh, yl, 0);

    uint32_t* curh = yh;
    uint32_t* curl = yl;
    uint32_t* nxth = xh;
    uint32_t* nxtl = xl;
    const size_t WT_OFF = (size_t)FDIM * FDIM / 2;

    for (int l = 0; l < 3; l++) {
        gemm_hmma_kernel<<<gemmGrid, 256, GEMM_SMEM>>>(
            curh, curl, wth + (l + 1) * WT_OFF, wtl + (l + 1) * WT_OFF,
            Wh, nullptr, nullptr, 1);
        wfuse_kernel<<<NN / 64, 256, WFUSE_SMEM>>>(Wh, al[l], whh, whl, f1, f2);
        rowmax_kernel<<<NN / 8, 256>>>(mask, f1, f2, m);
        attn_kernel<<<attnGrid, 256, ATTN_SMEM>>>(whh, whl, mask, f1, f2, m,
                                                  pacc, lpart);
        if (l == 2) {
            combine_kernel<<<NN * FDIM / 4 / 256, 256>>>(
                pacc, lpart, out, nullptr, nullptr, 1);
        } else {
            combine_kernel<<<NN * FDIM / 4 / 256, 256>>>(
                pacc, lpart, nullptr, nxth, nxtl, 0);
            uint32_t* th = curh; uint32_t* tl = curl;
            curh = nxth; curl = nxtl;
            nxth = th;  nxtl = tl;
        }
    }
}

// round 17
// speedup vs baseline: 1.1579x; 1.1579x over previous
#include <cuda_runtime.h>
#include <cuda_bf16.h>
#include <cstdint>

#define NN 4096
#define FDIM 256
#define ALPHA_LR 0.01f
#define NEG_INF_V -9.0e15f
#define ROWS 64
#define JSPLIT 4

// Scratch (allocation-free rule: __device__ globals)
__device__ __align__(16) float g_Wh[NN * FDIM];
__device__ float g_f1[NN];
__device__ float g_f2[NN];
__device__ float g_m[NN];
__device__ __align__(16) uint32_t g_mask[NN * NN / 32];   // 2MB bitmask
__device__ __align__(16) uint32_t g_whh[FDIM * NN / 2];   // WhT hi [f][j/2]
__device__ __align__(16) uint32_t g_whl[FDIM * NN / 2];   // WhT lo [f][j/2]
__device__ __align__(16) float g_pacc[JSPLIT * NN * FDIM]; // partial numerators
__device__ float g_lpart[JSPLIT * NN];                     // partial l sums
// packed h buffers (ping/pong): [m][k/2] bf16x2 hi/lo
__device__ __align__(16) uint32_t g_xh[NN * FDIM / 2];
__device__ __align__(16) uint32_t g_xl[NN * FDIM / 2];
__device__ __align__(16) uint32_t g_yh[NN * FDIM / 2];
__device__ __align__(16) uint32_t g_yl[NN * FDIM / 2];
// transposed weights: [4][n][k/2] bf16x2 hi/lo
__device__ __align__(16) uint32_t g_wth[4 * FDIM * FDIM / 2];
__device__ __align__(16) uint32_t g_wtl[4 * FDIM * FDIM / 2];

__device__ __forceinline__ uint32_t smem_u32(const void* p) {
    uint32_t a;
    asm("{ .reg .u64 t; cvta.to.shared.u64 t, %1; cvt.u32.u64 %0, t; }"
        : "=r"(a) : "l"(p));
    return a;
}

__device__ __forceinline__ void cp_async16(uint32_t s, const void* g) {
    asm volatile("cp.async.cg.shared.global [%0], [%1], 16;" :: "r"(s), "l"(g));
}
#define CP_COMMIT() asm volatile("cp.async.commit_group;" ::: "memory")
#define CP_WAIT0()  asm volatile("cp.async.wait_group 0;" ::: "memory")

// Truncation-based hi/lo split of a float pair:
//   hi = bits & 0xFFFF0000 (exact bf16), lo = bf16_rn(p - hi) (p - hi exact).
// hi pair packed with one PRMT; lo pair with one cvt.rn.bf16x2.f32.
__device__ __forceinline__ void split2(float pe, float po,
                                       uint32_t& hw, uint32_t& lw) {
    uint32_t ue = __float_as_uint(pe);
    uint32_t uo = __float_as_uint(po);
    asm("prmt.b32 %0, %1, %2, 0x7632;" : "=r"(hw) : "r"(ue), "r"(uo));
    float le = pe - __uint_as_float(ue & 0xFFFF0000u);
    float lo_ = po - __uint_as_float(uo & 0xFFFF0000u);
    __nv_bfloat162 l2 = __floats2bfloat162_rn(le, lo_);
    lw = *reinterpret_cast<uint32_t*>(&l2);
}

__device__ __forceinline__ void mma_bf16(float& d0, float& d1, float& d2, float& d3,
                                         uint32_t a0, uint32_t a1,
                                         uint32_t a2, uint32_t a3,
                                         uint32_t b0, uint32_t b1) {
    asm volatile(
        "mma.sync.aligned.m16n8k16.row.col.f32.bf16.bf16.f32 "
        "{%0,%1,%2,%3}, {%4,%5,%6,%7}, {%8,%9}, {%0,%1,%2,%3};"
        : "+f"(d0), "+f"(d1), "+f"(d2), "+f"(d3)
        : "r"(a0), "r"(a1), "r"(a2), "r"(a3), "r"(b0), "r"(b1));
}

__device__ __forceinline__ void ldsm_x4(uint32_t& r0, uint32_t& r1,
                                        uint32_t& r2, uint32_t& r3,
                                        uint32_t addr) {
    asm volatile("ldmatrix.sync.aligned.m8n8.x4.shared.b16 {%0,%1,%2,%3}, [%4];"
                 : "=r"(r0), "=r"(r1), "=r"(r2), "=r"(r3) : "r"(addr));
}

// ---------------------------------------------------------------------------
// Pack adj into bitmask
// ---------------------------------------------------------------------------
__global__ void pack_kernel(const int* __restrict__ adj,
                            uint32_t* __restrict__ mask) {
    const int lane = threadIdx.x & 31;
    const int gw = (blockIdx.x * 256 + threadIdx.x) >> 5;
    #pragma unroll 4
    for (int k = 0; k < 64; k++) {
        size_t word = (size_t)gw * 64 + k;
        int v = adj[word * 32 + lane];
        uint32_t b = __ballot_sync(0xffffffffu, v > 0);
        if (lane == 0) mask[word] = b;
    }
}

// ---------------------------------------------------------------------------
// hconv: X fp32 [4096][256] -> packed bf16x2 hi/lo [m][k/2]
// ---------------------------------------------------------------------------
__global__ __launch_bounds__(256)
void hconv_kernel(const float* __restrict__ X,
                  uint32_t* __restrict__ xh,
                  uint32_t* __restrict__ xl) {
    int v = blockIdx.x * 256 + threadIdx.x;
    int row = v >> 5;
    int c = v & 31;
    const float* src = &X[(size_t)row * FDIM + c * 8];
    float4 a = *reinterpret_cast<const float4*>(src);
    float4 b = *reinterpret_cast<const float4*>(src + 4);
    uint32_t hw[4], lw[4];
    split2(a.x, a.y, hw[0], lw[0]);
    split2(a.z, a.w, hw[1], lw[1]);
    split2(b.x, b.y, hw[2], lw[2]);
    split2(b.z, b.w, hw[3], lw[3]);
    size_t off = (size_t)row * 128 + c * 4;
    *reinterpret_cast<uint4*>(&xh[off]) = make_uint4(hw[0], hw[1], hw[2], hw[3]);
    *reinterpret_cast<uint4*>(&xl[off]) = make_uint4(lw[0], lw[1], lw[2], lw[3]);
}

// ---------------------------------------------------------------------------
// wtconv: W fp32 [k][n] -> WT packed [n][k/2] hi/lo. blockIdx.z picks matrix.
// ---------------------------------------------------------------------------
__global__ __launch_bounds__(256)
void wtconv_kernel(const float* __restrict__ W0, const float* __restrict__ W1,
                   const float* __restrict__ W2, const float* __restrict__ W3,
                   uint32_t* __restrict__ wth, uint32_t* __restrict__ wtl) {
    __shared__ float tile[64][33];
    const float* Ws[4] = {W0, W1, W2, W3};
    const float* W = Ws[blockIdx.z];
    uint32_t* oth = wth + (size_t)blockIdx.z * (FDIM * FDIM / 2);
    uint32_t* otl = wtl + (size_t)blockIdx.z * (FDIM * FDIM / 2);
    const int tid = threadIdx.x;
    const int kt = blockIdx.x * 64;
    const int nt = blockIdx.y * 32;
    {
        int r = tid >> 2;
        int c8 = (tid & 3) * 8;
        float4 v0 = *reinterpret_cast<const float4*>(&W[(size_t)(kt + r) * FDIM + nt + c8]);
        float4 v1 = *reinterpret_cast<const float4*>(&W[(size_t)(kt + r) * FDIM + nt + c8 + 4]);
        tile[r][c8 + 0] = v0.x; tile[r][c8 + 1] = v0.y;
        tile[r][c8 + 2] = v0.z; tile[r][c8 + 3] = v0.w;
        tile[r][c8 + 4] = v1.x; tile[r][c8 + 5] = v1.y;
        tile[r][c8 + 6] = v1.z; tile[r][c8 + 7] = v1.w;
    }
    __syncthreads();
    {
        int n = tid >> 3;
        int kp = (tid & 7) * 4;
        uint32_t hw[4], lw[4];
        #pragma unroll
        for (int q = 0; q < 4; q++) {
            int k = 2 * (kp + q);
            split2(tile[k][n], tile[k + 1][n], hw[q], lw[q]);
        }
        size_t off = (size_t)(nt + n) * (FDIM / 2) + (kt >> 1) + kp;
        *reinterpret_cast<uint4*>(&oth[off]) = make_uint4(hw[0], hw[1], hw[2], hw[3]);
        *reinterpret_cast<uint4*>(&otl[off]) = make_uint4(lw[0], lw[1], lw[2], lw[3]);
    }
}

// ---------------------------------------------------------------------------
// HMMA GEMM: C = A @ W. 64x64 tiles (2 CTAs/SM), grid (4, 64) = 256 CTAs.
// ---------------------------------------------------------------------------
__global__ __launch_bounds__(256, 2)
void gemm_hmma_kernel(const uint32_t* __restrict__ ah,
                      const uint32_t* __restrict__ al,
                      const uint32_t* __restrict__ wth,
                      const uint32_t* __restrict__ wtl,
                      float* __restrict__ Cf,
                      uint32_t* __restrict__ oh,
                      uint32_t* __restrict__ ol,
                      int mode) {
    extern __shared__ __align__(16) uint32_t ws[];
    const int tid  = threadIdx.x;
    const int lane = tid & 31;
    const int warp = tid >> 5;
    const int mq = warp & 1;
    const int nq = warp >> 1;
    const int m0 = blockIdx.y * 64;
    const int n0 = blockIdx.x * 64;
    const uint32_t sbase = smem_u32(ws);

    const int rowA  = lane & 15;
    const int koA   = lane >> 4;
    const int mlocB = lane >> 3;
    const int ntlB  = mlocB >> 1;
    const int koB   = mlocB & 1;
    const int rowBl = lane & 7;
    const int g    = lane >> 2;
    const int tig  = lane & 3;

    float acc[2][2][4] = {};

    auto stage = [&](int kc, int b) {
        uint32_t base = b * 8192u;
        #pragma unroll
        for (int k = 0; k < 4; k++) {
            int idx = k * 256 + tid;
            int half = idx >> 9;
            int rem  = idx & 511;
            int r = rem >> 3, c = rem & 7;
            const uint32_t* src = (half ? al : ah) +
                (size_t)(m0 + r) * 128 + kc * 32 + c * 4;
            cp_async16(sbase + (base + half * 2048u + r * 32 + ((c ^ (r & 7)) * 4)) * 4,
                       src);
        }
        #pragma unroll
        for (int k = 0; k < 4; k++) {
            int idx = k * 256 + tid;
            int half = idx >> 9;
            int rem  = idx & 511;
            int r = rem >> 3, c = rem & 7;
            const uint32_t* src = (half ? wtl : wth) +
                (size_t)(n0 + r) * 128 + kc * 32 + c * 4;
            cp_async16(sbase + (base + 4096u + half * 2048u + r * 32 +
                                ((c ^ (r & 7)) * 4)) * 4,
                       src);
        }
        CP_COMMIT();
    };

    stage(0, 0);
    CP_WAIT0();
    __syncthreads();

    for (int kc = 0; kc < 4; kc++) {
        if (kc < 3) stage(kc + 1, (kc + 1) & 1);
        const int b = kc & 1;
        const uint32_t AH = sbase + (b * 8192u) * 4;
        const uint32_t AL = AH + 2048u * 4;
        const uint32_t BH = sbase + (b * 8192u + 4096u) * 4;
        const uint32_t BL = BH + 2048u * 4;
        #pragma unroll
        for (int ksl = 0; ksl < 4; ksl++) {
            uint32_t ahf[2][4], alf[2][4];
            #pragma unroll
            for (int mt = 0; mt < 2; mt++) {
                int rin = mq * 32 + mt * 16 + rowA;
                uint32_t off = rin * 128 + (((2 * ksl + koA) ^ (rin & 7)) << 4);
                ldsm_x4(ahf[mt][0], ahf[mt][1], ahf[mt][2], ahf[mt][3], AH + off);
                ldsm_x4(alf[mt][0], alf[mt][1], alf[mt][2], alf[mt][3], AL + off);
            }
            int fin = nq * 16 + ntlB * 8 + rowBl;
            uint32_t boff = fin * 128 + (((2 * ksl + koB) ^ (fin & 7)) << 4);
            uint32_t bh0, bh1, bh2, bh3, bl0, bl1, bl2, bl3;
            ldsm_x4(bh0, bh1, bh2, bh3, BH + boff);
            ldsm_x4(bl0, bl1, bl2, bl3, BL + boff);
            #pragma unroll
            for (int mt = 0; mt < 2; mt++) {
                mma_bf16(acc[mt][0][0], acc[mt][0][1], acc[mt][0][2], acc[mt][0][3],
                         ahf[mt][0], ahf[mt][1], ahf[mt][2], ahf[mt][3], bh0, bh1);
                mma_bf16(acc[mt][0][0], acc[mt][0][1], acc[mt][0][2], acc[mt][0][3],
                         ahf[mt][0], ahf[mt][1], ahf[mt][2], ahf[mt][3], bl0, bl1);
                mma_bf16(acc[mt][0][0], acc[mt][0][1], acc[mt][0][2], acc[mt][0][3],
                         alf[mt][0], alf[mt][1], alf[mt][2], alf[mt][3], bh0, bh1);
                mma_bf16(acc[mt][1][0], acc[mt][1][1], acc[mt][1][2], acc[mt][1][3],
                         ahf[mt][0], ahf[mt][1], ahf[mt][2], ahf[mt][3], bh2, bh3);
                mma_bf16(acc[mt][1][0], acc[mt][1][1], acc[mt][1][2], acc[mt][1][3],
                         ahf[mt][0], ahf[mt][1], ahf[mt][2], ahf[mt][3], bl2, bl3);
                mma_bf16(acc[mt][1][0], acc[mt][1][1], acc[mt][1][2], acc[mt][1][3],
                         alf[mt][0], alf[mt][1], alf[mt][2], alf[mt][3], bh2, bh3);
            }
        }
        if (kc < 3) CP_WAIT0();
        __syncthreads();
    }

    #pragma unroll
    for (int mt = 0; mt < 2; mt++) {
        int r0 = m0 + mq * 32 + mt * 16 + g;
        int r1 = r0 + 8;
        #pragma unroll
        for (int nt = 0; nt < 2; nt++) {
            int f = n0 + nq * 16 + nt * 8 + 2 * tig;
            if (mode == 1) {
                *reinterpret_cast<float2*>(&Cf[(size_t)r0 * FDIM + f]) =
                    make_float2(acc[mt][nt][0], acc[mt][nt][1]);
                *reinterpret_cast<float2*>(&Cf[(size_t)r1 * FDIM + f]) =
                    make_float2(acc[mt][nt][2], acc[mt][nt][3]);
            } else {
                uint32_t hw, lw;
                split2(acc[mt][nt][0], acc[mt][nt][1], hw, lw);
                oh[(size_t)r0 * 128 + (f >> 1)] = hw;
                ol[(size_t)r0 * 128 + (f >> 1)] = lw;
                split2(acc[mt][nt][2], acc[mt][nt][3], hw, lw);
                oh[(size_t)r1 * 128 + (f >> 1)] = hw;
                ol[(size_t)r1 * 128 + (f >> 1)] = lw;
            }
        }
    }
}

// ---------------------------------------------------------------------------
// f1/f2 matvecs
// ---------------------------------------------------------------------------
__global__ void fvec_kernel(const float* __restrict__ Wh,
                            const float* __restrict__ a,
                            float* __restrict__ f1,
                            float* __restrict__ f2) {
    const int warp = threadIdx.x >> 5;
    const int lane = threadIdx.x & 31;
    const int row  = blockIdx.x * 8 + warp;
    float s1 = 0.f, s2 = 0.f;
    #pragma unroll
    for (int k = lane; k < FDIM; k += 32) {
        float w = Wh[row * FDIM + k];
        s1 += w * a[k];
        s2 += w * a[FDIM + k];
    }
    #pragma unroll
    for (int off = 16; off; off >>= 1) {
        s1 += __shfl_xor_sync(0xffffffffu, s1, off);
        s2 += __shfl_xor_sync(0xffffffffu, s2, off);
    }
    if (lane == 0) { f1[row] = s1; f2[row] = s2; }
}

// ---------------------------------------------------------------------------
// wconv: Wh[j][f] fp32 -> packed bf16x2 j-pair words [f][j/2], hi & lo
// ---------------------------------------------------------------------------
__global__ __launch_bounds__(256)
void wconv_kernel(const float* __restrict__ Wh,
                  uint32_t* __restrict__ whh,
                  uint32_t* __restrict__ whl) {
    __shared__ float tile[64][33];
    const int tid = threadIdx.x;
    const int jt = blockIdx.x * 64;
    const int ft = blockIdx.y * 32;
    {
        int r = tid >> 2;
        int c8 = (tid & 3) * 8;
        float4 v0 = *reinterpret_cast<const float4*>(
            &Wh[(size_t)(jt + r) * FDIM + ft + c8]);
        float4 v1 = *reinterpret_cast<const float4*>(
            &Wh[(size_t)(jt + r) * FDIM + ft + c8 + 4]);
        tile[r][c8 + 0] = v0.x; tile[r][c8 + 1] = v0.y;
        tile[r][c8 + 2] = v0.z; tile[r][c8 + 3] = v0.w;
        tile[r][c8 + 4] = v1.x; tile[r][c8 + 5] = v1.y;
        tile[r][c8 + 6] = v1.z; tile[r][c8 + 7] = v1.w;
    }
    __syncthreads();
    {
        int f = tid >> 3;
        int j2l = (tid & 7) * 4;
        uint32_t hw[4], lw[4];
        #pragma unroll
        for (int q = 0; q < 4; q++) {
            int j = 2 * (j2l + q);
            split2(tile[j][f], tile[j + 1][f], hw[q], lw[q]);
        }
        size_t off = (size_t)(ft + f) * (NN / 2) + (jt >> 1) + j2l;
        *reinterpret_cast<uint4*>(&whh[off]) = make_uint4(hw[0], hw[1], hw[2], hw[3]);
        *reinterpret_cast<uint4*>(&whl[off]) = make_uint4(lw[0], lw[1], lw[2], lw[3]);
    }
}

// ---------------------------------------------------------------------------
// Row max via monotonicity
// ---------------------------------------------------------------------------
__global__ __launch_bounds__(256)
void rowmax_kernel(const uint32_t* __restrict__ mask,
                   const float* __restrict__ f1,
                   const float* __restrict__ f2,
                   float* __restrict__ m) {
    __shared__ __align__(16) float f2s[NN];
    __shared__ uint32_t ms[8][128];
    const int tid  = threadIdx.x;
    const int lane = tid & 31;
    const int warp = tid >> 5;
    const int row0 = blockIdx.x * 8;

    #pragma unroll
    for (int k = 0; k < 4; k++) {
        int c = k * 256 + tid;
        reinterpret_cast<float4*>(f2s)[c] =
            reinterpret_cast<const float4*>(f2)[c];
    }
    #pragma unroll
    for (int k = 0; k < 4; k++) {
        int i = k * 256 + tid;
        ms[i >> 7][i & 127] = mask[(size_t)(row0 + (i >> 7)) * 128 + (i & 127)];
    }
    __syncthreads();

    float mx = -1.0e30f;
    #pragma unroll 8
    for (int k = 0; k < 128; k++) {
        uint32_t w = ms[warp][k];
        float v = f2s[k * 32 + lane];
        if ((w >> lane) & 1u) mx = fmaxf(mx, v);
    }
    #pragma unroll
    for (int off = 16; off; off >>= 1)
        mx = fmaxf(mx, __shfl_xor_sync(0xffffffffu, mx, off));
    if (lane == 0) {
        int row = row0 + warp;
        if (mx < -1.0e29f) {
            m[row] = NEG_INF_V;
        } else {
            float s = f1[row] + mx;
            m[row] = s > 0.f ? s : ALPHA_LR * s;
        }
    }
}

// ---------------------------------------------------------------------------
// Fused attention on HMMA: 64 rows x 256 f x j-quarter (32 tiles of 32 j).
// grid (64, 4) = 256 CTAs, 2 CTAs/SM (80 KB smem).
// ---------------------------------------------------------------------------
__global__ __launch_bounds__(256, 2)
void attn_kernel(const uint32_t* __restrict__ whh,
                 const uint32_t* __restrict__ whl,
                 const uint32_t* __restrict__ mask,
                 const float* __restrict__ f1,
                 const float* __restrict__ f2,
                 const float* __restrict__ m,
                 float* __restrict__ pacc,
                 float* __restrict__ lpart) {
    extern __shared__ __align__(16) uint32_t ws[];

    const int tid  = threadIdx.x;
    const int lane = tid & 31;
    const int warp = tid >> 5;
    const int g    = lane >> 2;
    const int tig  = lane & 3;
    const int row0 = blockIdx.x * ROWS;
    const int jq   = blockIdx.y;
    const uint32_t sbase = smem_u32(ws);

    const int prow = tid >> 2;
    const int jb8  = (tid & 3) * 8;
    const int grow = row0 + prow;
    const float f1r = f1[grow];
    const float mr  = m[grow];
    const uint32_t* mrow = mask + (size_t)grow * 128 + jq * 32;
    float ls = 0.f;

    float acc[4][4][4] = {};

    const int rowA  = lane & 15;
    const int koA   = lane >> 4;
    const int mlocB = lane >> 3;
    const int ntlB  = mlocB >> 1;
    const int koB   = mlocB & 1;
    const int rowBl = lane & 7;

    float4 fv0, fv1;
    uint32_t mw;

    fv0 = *reinterpret_cast<const float4*>(&f2[jq * 1024 + jb8]);
    fv1 = *reinterpret_cast<const float4*>(&f2[jq * 1024 + jb8 + 4]);
    mw  = mrow[0];
    #pragma unroll
    for (int k = 0; k < 8; k++) {
        int idx = k * 256 + tid;
        int half = idx >> 10;
        int rem  = idx & 1023;
        int f = rem >> 2, c = rem & 3;
        const uint32_t* src = (half ? whl : whh) +
            (size_t)f * (NN / 2) + jq * 512 + c * 4;
        cp_async16(sbase + (half * 4096 + f * 16 + ((c ^ ((f >> 1) & 3)) * 4)) * 4,
                   src);
    }
    CP_COMMIT();
    {
        uint32_t bits = (mw >> jb8) & 0xffu;
        const float fvr[8] = {fv0.x, fv0.y, fv0.z, fv0.w,
                              fv1.x, fv1.y, fv1.z, fv1.w};
        float pv[8];
        #pragma unroll
        for (int q = 0; q < 8; q++) {
            float s = f1r + fvr[q];
            float e = s > 0.f ? s : ALPHA_LR * s;
            float sc = ((bits >> q) & 1u) ? e : NEG_INF_V;
            pv[q] = __expf(sc - mr);
            ls += pv[q];
        }
        uint32_t hw[4], lw[4];
        #pragma unroll
        for (int u = 0; u < 4; u++) split2(pv[2 * u], pv[2 * u + 1], hw[u], lw[u]);
        int cb = tid & 3;
        uint32_t* ph = ws + 16384 + prow * 16;
        uint32_t* pl = ph + 1024;
        uint32_t so = (cb ^ ((prow >> 1) & 3)) * 4;
        *reinterpret_cast<uint4*>(ph + so) = make_uint4(hw[0], hw[1], hw[2], hw[3]);
        *reinterpret_cast<uint4*>(pl + so) = make_uint4(lw[0], lw[1], lw[2], lw[3]);
    }
    fv0 = *reinterpret_cast<const float4*>(&f2[jq * 1024 + 32 + jb8]);
    fv1 = *reinterpret_cast<const float4*>(&f2[jq * 1024 + 32 + jb8 + 4]);
    mw  = mrow[1];
    CP_WAIT0();
    __syncthreads();

    for (int t = 0; t < 32; t++) {
        if (t < 31) {
            const int b = (t + 1) & 1;
            #pragma unroll
            for (int k = 0; k < 8; k++) {
                int idx = k * 256 + tid;
                int half = idx >> 10;
                int rem  = idx & 1023;
                int f = rem >> 2, c = rem & 3;
                const uint32_t* src = (half ? whl : whh) +
                    (size_t)f * (NN / 2) + jq * 512 + (t + 1) * 16 + c * 4;
                cp_async16(sbase + (b * 8192 + half * 4096 + f * 16 +
                                    ((c ^ ((f >> 1) & 3)) * 4)) * 4,
                           src);
            }
            CP_COMMIT();
            uint32_t bits = (mw >> jb8) & 0xffu;
            const float fvr[8] = {fv0.x, fv0.y, fv0.z, fv0.w,
                                  fv1.x, fv1.y, fv1.z, fv1.w};
            float pv[8];
            #pragma unroll
            for (int q = 0; q < 8; q++) {
                float s = f1r + fvr[q];
                float e = s > 0.f ? s : ALPHA_LR * s;
                float sc = ((bits >> q) & 1u) ? e : NEG_INF_V;
                pv[q] = __expf(sc - mr);
                ls += pv[q];
            }
            uint32_t hw[4], lw[4];
            #pragma unroll
            for (int u = 0; u < 4; u++)
                split2(pv[2 * u], pv[2 * u + 1], hw[u], lw[u]);
            int cb = tid & 3;
            uint32_t* ph = ws + 16384 + b * 2048 + prow * 16;
            uint32_t* pl = ph + 1024;
            uint32_t so = (cb ^ ((prow >> 1) & 3)) * 4;
            *reinterpret_cast<uint4*>(ph + so) =
                make_uint4(hw[0], hw[1], hw[2], hw[3]);
            *reinterpret_cast<uint4*>(pl + so) =
                make_uint4(lw[0], lw[1], lw[2], lw[3]);
            int tn = (t + 2) & 31;
            fv0 = *reinterpret_cast<const float4*>(&f2[jq * 1024 + tn * 32 + jb8]);
            fv1 = *reinterpret_cast<const float4*>(&f2[jq * 1024 + tn * 32 + jb8 + 4]);
            mw  = mrow[tn];
        }

        {
            const int b = t & 1;
            const uint32_t BH = sbase + (b * 8192) * 4;
            const uint32_t BL = BH + 4096 * 4;
            const uint32_t PH = sbase + (16384 + b * 2048) * 4;
            const uint32_t PL = PH + 1024 * 4;
            #pragma unroll
            for (int ks = 0; ks < 2; ks++) {
                uint32_t ah[4][4], al[4][4];
                #pragma unroll
                for (int mt = 0; mt < 4; mt++) {
                    int rin = mt * 16 + rowA;
                    uint32_t off = rin * 64 +
                        (((2 * ks + koA) ^ ((rin >> 1) & 3)) << 4);
                    ldsm_x4(ah[mt][0], ah[mt][1], ah[mt][2], ah[mt][3], PH + off);
                    ldsm_x4(al[mt][0], al[mt][1], al[mt][2], al[mt][3], PL + off);
                }
                #pragma unroll
                for (int ntp = 0; ntp < 2; ntp++) {
                    int fin = warp * 32 + ntp * 16 + ntlB * 8 + rowBl;
                    uint32_t off = fin * 64 +
                        (((2 * ks + koB) ^ ((fin >> 1) & 3)) << 4);
                    uint32_t bh0, bh1, bh2, bh3, bl0, bl1, bl2, bl3;
                    ldsm_x4(bh0, bh1, bh2, bh3, BH + off);
                    ldsm_x4(bl0, bl1, bl2, bl3, BL + off);
                    #pragma unroll
                    for (int mt = 0; mt < 4; mt++) {
                        int n0 = ntp * 2;
                        mma_bf16(acc[mt][n0][0], acc[mt][n0][1],
                                 acc[mt][n0][2], acc[mt][n0][3],
                                 ah[mt][0], ah[mt][1], ah[mt][2], ah[mt][3],
                                 bh0, bh1);
                        mma_bf16(acc[mt][n0][0], acc[mt][n0][1],
                                 acc[mt][n0][2], acc[mt][n0][3],
                                 ah[mt][0], ah[mt][1], ah[mt][2], ah[mt][3],
                                 bl0, bl1);
                        mma_bf16(acc[mt][n0][0], acc[mt][n0][1],
                                 acc[mt][n0][2], acc[mt][n0][3],
                                 al[mt][0], al[mt][1], al[mt][2], al[mt][3],
                                 bh0, bh1);
                        mma_bf16(acc[mt][n0 + 1][0], acc[mt][n0 + 1][1],
                                 acc[mt][n0 + 1][2], acc[mt][n0 + 1][3],
                                 ah[mt][0], ah[mt][1], ah[mt][2], ah[mt][3],
                                 bh2, bh3);
                        mma_bf16(acc[mt][n0 + 1][0], acc[mt][n0 + 1][1],
                                 acc[mt][n0 + 1][2], acc[mt][n0 + 1][3],
                                 ah[mt][0], ah[mt][1], ah[mt][2], ah[mt][3],
                                 bl2, bl3);
                        mma_bf16(acc[mt][n0 + 1][0], acc[mt][n0 + 1][1],
                                 acc[mt][n0 + 1][2], acc[mt][n0 + 1][3],
                                 al[mt][0], al[mt][1], al[mt][2], al[mt][3],
                                 bh2, bh3);
                    }
                }
            }
        }
        if (t < 31) CP_WAIT0();
        __syncthreads();
    }

    ls += __shfl_xor_sync(0xffffffffu, ls, 1);
    ls += __shfl_xor_sync(0xffffffffu, ls, 2);
    if ((tid & 3) == 0) lpart[(size_t)jq * NN + grow] = ls;

    #pragma unroll
    for (int mt = 0; mt < 4; mt++) {
        int r0 = row0 + mt * 16 + g;
        int r1 = r0 + 8;
        #pragma unroll
        for (int nt = 0; nt < 4; nt++) {
            int f = warp * 32 + nt * 8 + 2 * tig;
            *reinterpret_cast<float2*>(
                &pacc[((size_t)jq * NN + r0) * FDIM + f]) =
                make_float2(acc[mt][nt][0], acc[mt][nt][1]);
            *reinterpret_cast<float2*>(
                &pacc[((size_t)jq * NN + r1) * FDIM + f]) =
                make_float2(acc[mt][nt][2], acc[mt][nt][3]);
        }
    }
}

// ---------------------------------------------------------------------------
// Combine 4 partials: v = ELU(Σnum/Σl); fp32 out (mode 1) or packed h (mode 0)
// ---------------------------------------------------------------------------
__global__ void combine_kernel(const float* __restrict__ pacc,
                               const float* __restrict__ lpart,
                               float* __restrict__ outf,
                               uint32_t* __restrict__ oh,
                               uint32_t* __restrict__ ol,
                               int mode) {
    int v = blockIdx.x * 256 + threadIdx.x;
    int row = v >> 6;
    int c = (v & 63) * 4;
    float4 o = make_float4(0.f, 0.f, 0.f, 0.f);
    float lsum = 0.f;
    #pragma unroll
    for (int q = 0; q < JSPLIT; q++) {
        float4 a = *reinterpret_cast<const float4*>(
            &pacc[((size_t)q * NN + row) * FDIM + c]);
        o.x += a.x; o.y += a.y; o.z += a.z; o.w += a.w;
        lsum += lpart[(size_t)q * NN + row];
    }
    float inv = 1.f / lsum;
    o.x *= inv; o.y *= inv; o.z *= inv; o.w *= inv;
    o.x = o.x > 0.f ? o.x : (__expf(o.x) - 1.f);
    o.y = o.y > 0.f ? o.y : (__expf(o.y) - 1.f);
    o.z = o.z > 0.f ? o.z : (__expf(o.z) - 1.f);
    o.w = o.w > 0.f ? o.w : (__expf(o.w) - 1.f);
    if (mode == 1) {
        *reinterpret_cast<float4*>(&outf[(size_t)row * FDIM + c]) = o;
    } else {
        uint32_t h0, l0, h1, l1;
        split2(o.x, o.y, h0, l0);
        split2(o.z, o.w, h1, l1);
        size_t off = (size_t)row * 128 + (c >> 1);
        *reinterpret_cast<uint2*>(&oh[off]) = make_uint2(h0, h1);
        *reinterpret_cast<uint2*>(&ol[off]) = make_uint2(l0, l1);
    }
}

// ---------------------------------------------------------------------------
extern "C" void kernel_launch(void* const* d_in, const int* in_sizes, int n_in,
                              void* d_out, int out_size) {
    const float* input = (const float*)d_in[0];
    const int*   adj   = (const int*)  d_in[1];
    const float* W0    = (const float*)d_in[2];
    const float* Wl[3] = {(const float*)d_in[3], (const float*)d_in[5],
                          (const float*)d_in[7]};
    const float* al[3] = {(const float*)d_in[4], (const float*)d_in[6],
                          (const float*)d_in[8]};
    float* out = (float*)d_out;

    float *Wh, *f1, *f2, *m, *pacc, *lpart;
    uint32_t *mask, *whh, *whl, *xh, *xl, *yh, *yl, *wth, *wtl;
    cudaGetSymbolAddress((void**)&Wh,    g_Wh);
    cudaGetSymbolAddress((void**)&f1,    g_f1);
    cudaGetSymbolAddress((void**)&f2,    g_f2);
    cudaGetSymbolAddress((void**)&m,     g_m);
    cudaGetSymbolAddress((void**)&mask,  g_mask);
    cudaGetSymbolAddress((void**)&whh,   g_whh);
    cudaGetSymbolAddress((void**)&whl,   g_whl);
    cudaGetSymbolAddress((void**)&pacc,  g_pacc);
    cudaGetSymbolAddress((void**)&lpart, g_lpart);
    cudaGetSymbolAddress((void**)&xh,    g_xh);
    cudaGetSymbolAddress((void**)&xl,    g_xl);
    cudaGetSymbolAddress((void**)&yh,    g_yh);
    cudaGetSymbolAddress((void**)&yl,    g_yl);
    cudaGetSymbolAddress((void**)&wth,   g_wth);
    cudaGetSymbolAddress((void**)&wtl,   g_wtl);

    const int ATTN_SMEM = 20480 * 4;               // 80 KB -> 2 CTAs/SM
    const int GEMM_SMEM = 16384 * 4;               // 64 KB -> 2 CTAs/SM
    static bool attr_set = false;
    if (!attr_set) {
        cudaFuncSetAttribute(attn_kernel,
                             cudaFuncAttributeMaxDynamicSharedMemorySize,
                             ATTN_SMEM);
        cudaFuncSetAttribute(gemm_hmma_kernel,
                             cudaFuncAttributeMaxDynamicSharedMemorySize,
                             GEMM_SMEM);
        attr_set = true;
    }

    dim3 gemmGrid(FDIM / 64, NN / 64);             // (4, 64) = 256 CTAs
    dim3 wconvGrid(NN / 64, FDIM / 32);            // (64, 8) = 512 CTAs
    dim3 wtGrid(FDIM / 64, FDIM / 32, 4);          // (4, 8, 4)
    dim3 attnGrid(NN / ROWS, JSPLIT);              // (64, 4) = 256 CTAs

    pack_kernel<<<1024, 256>>>(adj, mask);
    wtconv_kernel<<<wtGrid, 256>>>(W0, Wl[0], Wl[1], Wl[2], wth, wtl);
    hconv_kernel<<<512, 256>>>(input, xh, xl);
    gemm_hmma_kernel<<<gemmGrid, 256, GEMM_SMEM>>>(
        xh, xl, wth, wtl, nullptr, yh, yl, 0);

    uint32_t* curh = yh;
    uint32_t* curl = yl;
    uint32_t* nxth = xh;
    uint32_t* nxtl = xl;
    const size_t WT_OFF = (size_t)FDIM * FDIM / 2;

    for (int l = 0; l < 3; l++) {
        gemm_hmma_kernel<<<gemmGrid, 256, GEMM_SMEM>>>(
            curh, curl, wth + (l + 1) * WT_OFF, wtl + (l + 1) * WT_OFF,
            Wh, nullptr, nullptr, 1);
        fvec_kernel<<<NN / 8, 256>>>(Wh, al[l], f1, f2);
        rowmax_kernel<<<NN / 8, 256>>>(mask, f1, f2, m);
        wconv_kernel<<<wconvGrid, 256>>>(Wh, whh, whl);
        attn_kernel<<<attnGrid, 256, ATTN_SMEM>>>(whh, whl, mask, f1, f2, m,
                                                  pacc, lpart);
        if (l == 2) {
            combine_kernel<<<NN * FDIM / 4 / 256, 256>>>(
                pacc, lpart, out, nullptr, nullptr, 1);
        } else {
            combine_kernel<<<NN * FDIM / 4 / 256, 256>>>(
                pacc, lpart, nullptr, nxth, nxtl, 0);
            uint32_t* th = curh; uint32_t* tl = curl;
            curh = nxth; curl = nxtl;
            nxth = th;  nxtl = tl;
        }
    }
}